// round 16
// baseline (speedup 1.0000x reference)
#include <cuda_runtime.h>
#include <cuda_fp16.h>
#include <cstdint>

#define T_TOK 2048
#define H_DIM 2048
#define F_DIM 1408
#define SF_DIM 2816
#define N_EXP 8

#define BK 64
#define STAGES 3
#define APITCH 144                               // A smem row: 64 halves + pad
#define BPITCH 272                               // B smem row: 128 halves + pad
#define ACT_STAGE_B (128 * APITCH + 2 * 64 * BPITCH)   // 53248
#define DOWN_STAGE_B (128 * APITCH + 64 * BPITCH)      // 35840
#define ACT_SMEM (STAGES * ACT_STAGE_B)          // 159744 B
#define DOWN_SMEM (STAGES * DOWN_STAGE_B)        // 107520 B

// ---- scratch (device globals: no allocations allowed) ----
__device__ int    g_count[N_EXP];
__device__ int    g_perm[N_EXP * T_TOK];
__device__ int    g_slot[2 * T_TOK];
__device__ float  g_tokw[2 * T_TOK];
__device__ __half g_xh  [(size_t)T_TOK * H_DIM];
__device__ __half g_w1h [(size_t)N_EXP * H_DIM * F_DIM];  // gate_proj fp16, orig layout
__device__ __half g_w2h [(size_t)N_EXP * H_DIM * F_DIM];  // up_proj fp16
__device__ __half g_wdh [(size_t)N_EXP * F_DIM * H_DIM];  // down_proj fp16
__device__ __half g_sgh [(size_t)H_DIM * SF_DIM];
__device__ __half g_suh [(size_t)H_DIM * SF_DIM];
__device__ __half g_sdh [(size_t)SF_DIM * H_DIM];
__device__ __half g_acth[(size_t)N_EXP * T_TOK * F_DIM];
__device__ __half g_sacth[(size_t)T_TOK * SF_DIM];
__device__ float  g_dout[(size_t)N_EXP * T_TOK * H_DIM];

// ---------------------------------------------------------------------------
__device__ __forceinline__ uint32_t smem_u32(const void* p) {
    uint32_t a;
    asm("{ .reg .u64 t; cvta.to.shared.u64 t, %1; cvt.u32.u64 %0, t; }" : "=r"(a) : "l"(p));
    return a;
}
__device__ __forceinline__ void cpa16s(uint32_t sa, const void* g) {
    asm volatile("cp.async.cg.shared.global [%0], [%1], 16;" :: "r"(sa), "l"(g));
}
#define CP_COMMIT asm volatile("cp.async.commit_group;" ::: "memory")
#define CP_WAIT(n) asm volatile("cp.async.wait_group %0;" :: "n"(n) : "memory")

__device__ __forceinline__ void mma16(float* c, const uint32_t* a, uint32_t b0, uint32_t b1) {
    asm volatile(
        "mma.sync.aligned.m16n8k16.row.col.f32.f16.f16.f32 "
        "{%0,%1,%2,%3}, {%4,%5,%6,%7}, {%8,%9}, {%0,%1,%2,%3};"
        : "+f"(c[0]), "+f"(c[1]), "+f"(c[2]), "+f"(c[3])
        : "r"(a[0]), "r"(a[1]), "r"(a[2]), "r"(a[3]), "r"(b0), "r"(b1));
}
__device__ __forceinline__ void ldsm4(uint32_t* r, uint32_t addr) {
    asm volatile("ldmatrix.sync.aligned.m8n8.x4.shared.b16 {%0,%1,%2,%3}, [%4];"
        : "=r"(r[0]), "=r"(r[1]), "=r"(r[2]), "=r"(r[3]) : "r"(addr));
}
__device__ __forceinline__ void ldsm4t(uint32_t* r, uint32_t addr) {
    asm volatile("ldmatrix.sync.aligned.m8n8.x4.trans.shared.b16 {%0,%1,%2,%3}, [%4];"
        : "=r"(r[0]), "=r"(r[1]), "=r"(r[2]), "=r"(r[3]) : "r"(addr));
}

// ---------------------------------------------------------------------------
__global__ void zero_counts_kernel() {
    if (threadIdx.x < N_EXP) g_count[threadIdx.x] = 0;
}

// fp32 -> fp16 streaming convert (no transpose)
__global__ void f2h_kernel(const float4* __restrict__ in, uint2* __restrict__ outp, int n4) {
    int stride = gridDim.x * blockDim.x;
    for (int i = blockIdx.x * blockDim.x + threadIdx.x; i < n4; i += stride) {
        float4 v = in[i];
        __half2 lo = __floats2half2_rn(v.x, v.y);
        __half2 hi = __floats2half2_rn(v.z, v.w);
        outp[i] = make_uint2(*(uint32_t*)&lo, *(uint32_t*)&hi);
    }
}

// ---------------------------------------------------------------------------
// gate + top-2 routing; also emits the fp16 copy of x (fused f2h)
__global__ void gate_topk_kernel(const float* __restrict__ x,
                                 const float* __restrict__ gw) {
    __shared__ float xs[H_DIM];
    __shared__ float logits[N_EXP];
    int t = blockIdx.x;
    const float4* xr = (const float4*)(x + (size_t)t * H_DIM);
    for (int i = threadIdx.x; i < H_DIM / 4; i += blockDim.x)
        ((float4*)xs)[i] = xr[i];
    __syncthreads();

    for (int i = threadIdx.x; i < H_DIM / 2; i += blockDim.x) {
        __half2 v = __floats2half2_rn(xs[2 * i], xs[2 * i + 1]);
        *(__half2*)(g_xh + (size_t)t * H_DIM + 2 * i) = v;
    }

    int w = threadIdx.x >> 5, lane = threadIdx.x & 31;
    if (w < N_EXP) {
        const float* gr = gw + (size_t)w * H_DIM;
        float s = 0.f;
        for (int i = lane; i < H_DIM; i += 32) s += xs[i] * gr[i];
        #pragma unroll
        for (int o = 16; o; o >>= 1) s += __shfl_xor_sync(0xffffffffu, s, o);
        if (lane == 0) logits[w] = s;
    }
    __syncthreads();

    if (threadIdx.x == 0) {
        float m = logits[0];
        #pragma unroll
        for (int e = 1; e < N_EXP; e++) m = fmaxf(m, logits[e]);
        float p[N_EXP]; float sum = 0.f;
        #pragma unroll
        for (int e = 0; e < N_EXP; e++) { p[e] = expf(logits[e] - m); sum += p[e]; }
        float inv = 1.f / sum;
        int i0 = 0;
        #pragma unroll
        for (int e = 1; e < N_EXP; e++) if (p[e] > p[i0]) i0 = e;
        int i1 = (i0 == 0) ? 1 : 0;
        #pragma unroll
        for (int e = 0; e < N_EXP; e++) if (e != i0 && p[e] > p[i1]) i1 = e;

        int s0 = atomicAdd(&g_count[i0], 1);
        g_perm[i0 * T_TOK + s0] = t;
        g_slot[2 * t]     = i0 * T_TOK + s0;
        g_tokw[2 * t]     = p[i0] * inv;
        int s1 = atomicAdd(&g_count[i1], 1);
        g_perm[i1 * T_TOK + s1] = t;
        g_slot[2 * t + 1] = i1 * T_TOK + s1;
        g_tokw[2 * t + 1] = p[i1] * inv;
    }
}

// ---------------------------------------------------------------------------
__global__ void combine_kernel(float* __restrict__ out) {
    int t = blockIdx.x;
    int s0 = g_slot[2 * t], s1 = g_slot[2 * t + 1];
    float w0 = g_tokw[2 * t], w1 = g_tokw[2 * t + 1];
    const float4* d0 = (const float4*)(g_dout + (size_t)s0 * H_DIM);
    const float4* d1 = (const float4*)(g_dout + (size_t)s1 * H_DIM);
    float4* o = (float4*)(out + (size_t)t * H_DIM);
    for (int i = threadIdx.x; i < H_DIM / 4; i += blockDim.x) {
        float4 a = o[i], b = d0[i], c = d1[i];
        a.x += w0 * b.x + w1 * c.x;
        a.y += w0 * b.y + w1 * c.y;
        a.z += w0 * b.z + w1 * c.z;
        a.w += w0 * b.w + w1 * c.w;
        o[i] = a;
    }
}

// ---------------------------------------------------------------------------
// act: out_fp16 = silu(A@W1) * (A@W2). W1/W2 in ORIGINAL [K][N] layout (n
// contiguous); B fragments via ldmatrix.x4.trans. 512 threads, block 128x128,
// warp tile 32x32, BK=64, 3-stage cp.async.
template <bool ROUTED>
__global__ void __launch_bounds__(512)
act_kernel(const __half* __restrict__ Ax,
           const __half* __restrict__ B1base,
           const __half* __restrict__ B2base,
           __half* __restrict__ outBase,
           int nld) {    // nld = N total (B row pitch & out pitch); K = H_DIM
    extern __shared__ __half smem[];
    __shared__ int stok[128];
    const int KD = H_DIM;

    int e = ROUTED ? blockIdx.z : 0;
    int cnt = ROUTED ? g_count[e] : T_TOK;
    int m0 = blockIdx.y * 128;
    if (m0 >= cnt) return;
    int n0 = blockIdx.x * 128;
    int tid = threadIdx.x, wid = tid >> 5, lane = tid & 31;
    int g = lane >> 2, tg = lane & 3;
    int wm = wid & 3, wn = wid >> 2;

    if (tid < 128) {
        int slot = m0 + tid;
        stok[tid] = ROUTED ? ((slot < cnt) ? g_perm[e * T_TOK + slot]
                                           : g_perm[e * T_TOK]) : slot;
    }
    __syncthreads();

    const __half* B1 = B1base + (ROUTED ? (size_t)e * H_DIM * F_DIM : 0);
    const __half* B2 = B2base + (ROUTED ? (size_t)e * H_DIM * F_DIM : 0);
    __half* outE = outBase + (ROUTED ? (size_t)e * T_TOK * nld : 0);
    uint32_t sbase = smem_u32(smem);

    // A fragments: non-trans ldmatrix on K-major A tile
    uint32_t aOff = (uint32_t)((wm * 32 + (lane & 15)) * APITCH + (lane >> 4) * 16);
    // B fragments: trans ldmatrix on [K][N] tile.
    // lanes 0-7: (k0-7, n0); 8-15: (k8-15, n0); 16-23: (k0-7, n0+8); 24-31: (k8-15, n0+8)
    int krow = (lane & 7) + ((lane >> 3) & 1) * 8;
    uint32_t bOff = (uint32_t)(krow * BPITCH + (wn * 32 + (lane >> 4) * 8) * 2);

    // per stage: A rows [0,128) @APITCH; B1 64 rows @BPITCH; B2 64 rows @BPITCH
    #define ACT_LOAD(st, k0) {                                                  \
        uint32_t base = sbase + (st) * ACT_STAGE_B;                             \
        uint32_t b1s = base + 128 * APITCH;                                     \
        uint32_t b2s = b1s + 64 * BPITCH;                                       \
        _Pragma("unroll")                                                       \
        for (int i = 0; i < 2; i++) {                                           \
            int id = tid + i * 512;                                             \
            int ra = id >> 3, ja = id & 7;                                      \
            cpa16s(base + ra * APITCH + ja * 16,                                \
                   Ax + (size_t)stok[ra] * KD + (k0) + ja * 8);                 \
            int rb = id >> 4, jb = id & 15;                                     \
            size_t go = (size_t)((k0) + rb) * nld + n0 + jb * 8;                \
            cpa16s(b1s + rb * BPITCH + jb * 16, B1 + go);                       \
            cpa16s(b2s + rb * BPITCH + jb * 16, B2 + go);                       \
        }                                                                       \
        CP_COMMIT;                                                              \
    }

    float acc1[2][4][4], acc2[2][4][4];
    #pragma unroll
    for (int mt = 0; mt < 2; mt++)
        #pragma unroll
        for (int nt = 0; nt < 4; nt++)
            #pragma unroll
            for (int q = 0; q < 4; q++) { acc1[mt][nt][q] = 0.f; acc2[mt][nt][q] = 0.f; }

    const int NIT = KD / BK;   // 32
    ACT_LOAD(0, 0);
    ACT_LOAD(1, BK);

    for (int it = 0; it < NIT; ++it) {
        if (it + 1 < NIT) CP_WAIT(1); else CP_WAIT(0);
        __syncthreads();
        if (it + 2 < NIT) ACT_LOAD((it + 2) % STAGES, (it + 2) * BK);

        uint32_t stg = sbase + (it % STAGES) * ACT_STAGE_B;
        uint32_t aB = stg + aOff;
        uint32_t b1B = stg + 128 * APITCH + bOff;
        uint32_t b2B = stg + 128 * APITCH + 64 * BPITCH + bOff;

        #pragma unroll
        for (int s = 0; s < 4; s++) {   // four k16 steps
            uint32_t a[2][4];
            #pragma unroll
            for (int mt = 0; mt < 2; mt++)
                ldsm4(a[mt], aB + mt * (16 * APITCH) + s * 32);
            #pragma unroll
            for (int p = 0; p < 2; p++) {   // n16 pairs within warp's 32 cols
                uint32_t rb1[4], rb2[4];
                ldsm4t(rb1, b1B + s * (16 * BPITCH) + p * 32);
                ldsm4t(rb2, b2B + s * (16 * BPITCH) + p * 32);
                #pragma unroll
                for (int mt = 0; mt < 2; mt++) {
                    mma16(acc1[mt][2 * p],     a[mt], rb1[0], rb1[1]);
                    mma16(acc1[mt][2 * p + 1], a[mt], rb1[2], rb1[3]);
                    mma16(acc2[mt][2 * p],     a[mt], rb2[0], rb2[1]);
                    mma16(acc2[mt][2 * p + 1], a[mt], rb2[2], rb2[3]);
                }
            }
        }
    }
    #undef ACT_LOAD

    #pragma unroll
    for (int mt = 0; mt < 2; mt++) {
        #pragma unroll
        for (int nt = 0; nt < 4; nt++) {
            float v[4];
            #pragma unroll
            for (int q = 0; q < 4; q++) {
                float gv = acc1[mt][nt][q], uv = acc2[mt][nt][q];
                v[q] = (gv / (1.f + __expf(-gv))) * uv;
            }
            __half2 lo = __floats2half2_rn(v[0], v[1]);
            __half2 hi = __floats2half2_rn(v[2], v[3]);
            int row = m0 + wm * 32 + mt * 16 + g;
            int col = n0 + wn * 32 + nt * 8 + tg * 2;
            *(uint32_t*)(outE + (size_t)row * nld + col)       = *(uint32_t*)&lo;
            *(uint32_t*)(outE + (size_t)(row + 8) * nld + col) = *(uint32_t*)&hi;
        }
    }
}

// ---------------------------------------------------------------------------
// down: C = A @ Wd. Wd in ORIGINAL [K][H] layout; B frags via ldmatrix.trans.
template <bool ROUTED>
__global__ void __launch_bounds__(512)
down_kernel(const __half* __restrict__ Abase,
            const __half* __restrict__ Bbase,
            float* __restrict__ out,
            int KD) {
    extern __shared__ __half smem[];

    int e = ROUTED ? blockIdx.z : 0;
    int cnt = ROUTED ? g_count[e] : T_TOK;
    int m0 = blockIdx.y * 128;
    if (m0 >= cnt) return;
    int n0 = blockIdx.x * 128;
    int tid = threadIdx.x, wid = tid >> 5, lane = tid & 31;
    int g = lane >> 2, tg = lane & 3;
    int wm = wid & 3, wn = wid >> 2;

    const __half* A = Abase + (ROUTED ? (size_t)e * T_TOK * KD : 0);
    const __half* B = Bbase + (ROUTED ? (size_t)e * KD * H_DIM : 0);
    float* outE = out + (ROUTED ? (size_t)e * T_TOK * H_DIM : 0);
    uint32_t sbase = smem_u32(smem);

    uint32_t aOff = (uint32_t)((wm * 32 + (lane & 15)) * APITCH + (lane >> 4) * 16);
    int krow = (lane & 7) + ((lane >> 3) & 1) * 8;
    uint32_t bOff = (uint32_t)(krow * BPITCH + (wn * 32 + (lane >> 4) * 8) * 2);

    #define DOWN_LOAD(st, k0) {                                                 \
        uint32_t base = sbase + (st) * DOWN_STAGE_B;                            \
        uint32_t bs = base + 128 * APITCH;                                      \
        _Pragma("unroll")                                                       \
        for (int i = 0; i < 2; i++) {                                           \
            int id = tid + i * 512;                                             \
            int ra = id >> 3, ja = id & 7;                                      \
            cpa16s(base + ra * APITCH + ja * 16,                                \
                   A + (size_t)(m0 + ra) * KD + (k0) + ja * 8);                 \
            int rb = id >> 4, jb = id & 15;                                     \
            cpa16s(bs + rb * BPITCH + jb * 16,                                  \
                   B + (size_t)((k0) + rb) * H_DIM + n0 + jb * 8);              \
        }                                                                       \
        CP_COMMIT;                                                              \
    }

    float acc[2][4][4];
    #pragma unroll
    for (int mt = 0; mt < 2; mt++)
        #pragma unroll
        for (int nt = 0; nt < 4; nt++)
            #pragma unroll
            for (int q = 0; q < 4; q++) acc[mt][nt][q] = 0.f;

    const int NIT = KD / BK;   // 22 or 44
    DOWN_LOAD(0, 0);
    DOWN_LOAD(1, BK);

    for (int it = 0; it < NIT; ++it) {
        if (it + 1 < NIT) CP_WAIT(1); else CP_WAIT(0);
        __syncthreads();
        if (it + 2 < NIT) DOWN_LOAD((it + 2) % STAGES, (it + 2) * BK);

        uint32_t stg = sbase + (it % STAGES) * DOWN_STAGE_B;
        uint32_t aB = stg + aOff;
        uint32_t bB = stg + 128 * APITCH + bOff;

        #pragma unroll
        for (int s = 0; s < 4; s++) {
            uint32_t a[2][4];
            #pragma unroll
            for (int mt = 0; mt < 2; mt++)
                ldsm4(a[mt], aB + mt * (16 * APITCH) + s * 32);
            #pragma unroll
            for (int p = 0; p < 2; p++) {
                uint32_t rb[4];
                ldsm4t(rb, bB + s * (16 * BPITCH) + p * 32);
                #pragma unroll
                for (int mt = 0; mt < 2; mt++) {
                    mma16(acc[mt][2 * p],     a[mt], rb[0], rb[1]);
                    mma16(acc[mt][2 * p + 1], a[mt], rb[2], rb[3]);
                }
            }
        }
    }
    #undef DOWN_LOAD

    #pragma unroll
    for (int mt = 0; mt < 2; mt++) {
        #pragma unroll
        for (int half = 0; half < 2; half++) {
            int rl = wm * 32 + mt * 16 + g + half * 8;
            float* dst = outE + (size_t)(m0 + rl) * H_DIM + n0;
            #pragma unroll
            for (int nt = 0; nt < 4; nt++) {
                int col = wn * 32 + nt * 8 + tg * 2;
                *(float2*)(dst + col) =
                    make_float2(acc[mt][nt][half * 2 + 0], acc[mt][nt][half * 2 + 1]);
            }
        }
    }
}

// ---------------------------------------------------------------------------
extern "C" void kernel_launch(void* const* d_in, const int* in_sizes, int n_in,
                              void* d_out, int out_size) {
    const float* x  = (const float*)d_in[0];
    const float* gw = (const float*)d_in[1];
    const float* gp = (const float*)d_in[2];
    const float* up = (const float*)d_in[3];
    const float* dp = (const float*)d_in[4];
    const float* sg = (const float*)d_in[5];
    const float* su = (const float*)d_in[6];
    const float* sd = (const float*)d_in[7];
    float* out = (float*)d_out;

    __half *xhP, *w1hP, *w2hP, *wdhP, *sghP, *suhP, *sdhP, *acthP, *sacthP;
    float* doutP;
    cudaGetSymbolAddress((void**)&xhP,    g_xh);
    cudaGetSymbolAddress((void**)&w1hP,   g_w1h);
    cudaGetSymbolAddress((void**)&w2hP,   g_w2h);
    cudaGetSymbolAddress((void**)&wdhP,   g_wdh);
    cudaGetSymbolAddress((void**)&sghP,   g_sgh);
    cudaGetSymbolAddress((void**)&suhP,   g_suh);
    cudaGetSymbolAddress((void**)&sdhP,   g_sdh);
    cudaGetSymbolAddress((void**)&acthP,  g_acth);
    cudaGetSymbolAddress((void**)&sacthP, g_sacth);
    cudaGetSymbolAddress((void**)&doutP,  g_dout);

    cudaFuncSetAttribute(act_kernel<true>,   cudaFuncAttributeMaxDynamicSharedMemorySize, ACT_SMEM);
    cudaFuncSetAttribute(act_kernel<false>,  cudaFuncAttributeMaxDynamicSharedMemorySize, ACT_SMEM);
    cudaFuncSetAttribute(down_kernel<true>,  cudaFuncAttributeMaxDynamicSharedMemorySize, DOWN_SMEM);
    cudaFuncSetAttribute(down_kernel<false>, cudaFuncAttributeMaxDynamicSharedMemorySize, DOWN_SMEM);

    // one-time side streams + events (created outside graph capture)
    static cudaStream_t s1 = nullptr, s2 = nullptr;
    static cudaEvent_t evRoot = nullptr, evFork = nullptr, evJoin = nullptr,
                       evDp = nullptr, evSu = nullptr, evSd = nullptr;
    if (s1 == nullptr) {
        cudaStreamCreateWithFlags(&s1, cudaStreamNonBlocking);
        cudaStreamCreateWithFlags(&s2, cudaStreamNonBlocking);
        cudaEventCreateWithFlags(&evRoot, cudaEventDisableTiming);
        cudaEventCreateWithFlags(&evFork, cudaEventDisableTiming);
        cudaEventCreateWithFlags(&evJoin, cudaEventDisableTiming);
        cudaEventCreateWithFlags(&evDp,   cudaEventDisableTiming);
        cudaEventCreateWithFlags(&evSu,   cudaEventDisableTiming);
        cudaEventCreateWithFlags(&evSd,   cudaEventDisableTiming);
    }

    const int NW4 = (N_EXP * H_DIM * F_DIM) / 4;   // gp/up/dp float4 count
    const int NS4 = (H_DIM * SF_DIM) / 4;          // sg/su/sd float4 count

    // s0: root (side streams join capture via an event recorded here)
    zero_counts_kernel<<<1, 32>>>();
    cudaEventRecord(evRoot, 0);

    // s0: gating (also produces xh) — concurrent with converts below
    gate_topk_kernel<<<T_TOK, 256>>>(x, gw);
    cudaEventRecord(evFork, 0);

    // s1: join capture, then gate/up weight converts (independent of gate)
    cudaStreamWaitEvent(s1, evRoot, 0);
    f2h_kernel<<<2048, 256, 0, s1>>>((const float4*)gp, (uint2*)w1hP, NW4);
    f2h_kernel<<<2048, 256, 0, s1>>>((const float4*)up, (uint2*)w2hP, NW4);

    // s2: join capture, then dp + shared weight converts (independent of gate)
    cudaStreamWaitEvent(s2, evRoot, 0);
    f2h_kernel<<<2048, 256, 0, s2>>>((const float4*)dp, (uint2*)wdhP, NW4);
    cudaEventRecord(evDp, s2);
    f2h_kernel<<<2048, 256, 0, s2>>>((const float4*)sg, (uint2*)sghP, NS4);
    f2h_kernel<<<2048, 256, 0, s2>>>((const float4*)su, (uint2*)suhP, NS4);
    cudaEventRecord(evSu, s2);
    f2h_kernel<<<2048, 256, 0, s2>>>((const float4*)sd, (uint2*)sdhP, NS4);
    cudaEventRecord(evSd, s2);

    // s1: routed chain (act needs gate + xh; down needs dp convert)
    cudaStreamWaitEvent(s1, evFork, 0);
    act_kernel<true><<<dim3(F_DIM / 128, T_TOK / 128, N_EXP), 512, ACT_SMEM, s1>>>(xhP, w1hP, w2hP, acthP, F_DIM);
    cudaStreamWaitEvent(s1, evDp, 0);
    down_kernel<true><<<dim3(H_DIM / 128, T_TOK / 128, N_EXP), 512, DOWN_SMEM, s1>>>(acthP, wdhP, doutP, F_DIM);
    cudaEventRecord(evJoin, s1);

    // s0: shared chain (act needs sg/su + xh from gate on this stream)
    cudaStreamWaitEvent(0, evSu, 0);
    act_kernel<false><<<dim3(SF_DIM / 128, T_TOK / 128, 1), 512, ACT_SMEM>>>(xhP, sghP, suhP, sacthP, SF_DIM);
    cudaStreamWaitEvent(0, evSd, 0);
    down_kernel<false><<<dim3(H_DIM / 128, T_TOK / 128, 1), 512, DOWN_SMEM>>>(sacthP, sdhP, out, SF_DIM);

    // join: combine needs both chains
    cudaStreamWaitEvent(0, evJoin, 0);
    combine_kernel<<<T_TOK, 256>>>(out);
}